// round 6
// baseline (speedup 1.0000x reference)
#include <cuda_runtime.h>
#include <cuda_fp16.h>
#include <math.h>
#include <stdint.h>

// ---------------------------------------------------------------------------
// SwinV2 block: B=32, H=W=48, C=384, NH=12, HD=32, WS=12, N=144, SHIFT=6
// GEMMs: fp16 hi/lo 3-term mma.m16n8k16 (fp32 accum), cp.async 2-stage.
// ---------------------------------------------------------------------------
namespace {
constexpr int kH = 48;
constexpr int kW = 48;
constexpr int kC = 384;
constexpr int kNH = 12;
constexpr int kHD = 32;
constexpr int kWS = 12;
constexpr int kN = 144;
constexpr int kSHIFT = 6;
constexpr int kM = 73728;        // 512 windows * 144 tokens
constexpr long kSLOT = 28311552; // kM * kC elements

constexpr int ST2 = 20;          // smem row stride in 32-bit words (40 halves)
constexpr int BUFW = 128 * ST2;  // words per operand buffer (2560)
constexpr int STAGEW = 4 * BUFW; // Ahi|Alo|Bhi|Blo per stage (10240 words)
constexpr int SMEM_DYN = 2 * STAGEW * 4;  // 81920 B

// fp16 weight-split offsets (halves), [n][k] layout
constexpr long OQKV = 0;        // 1152 x 384
constexpr long OPROJ = 442368;  // 384 x 384
constexpr long OFC1 = 589824;   // 1536 x 384
constexpr long OFC2 = 1179648;  // 384 x 1536
}

// scratch slots (28311552 f32 each):
// s0 q | s1 k -> x1 f32 | s2 v -> h_hi(spans s2,s3) | s3 attn hi/lo
// s4 x hi/lo -> x1 hi/lo | s5 proj_out f32 -> h_lo(spans s5,s6) | s7 fc2_out
__device__ float g_scratch[8 * 28311552ULL];
__device__ float g_btab[529 * 12];
__device__ float g_bias2[16 * 12 * 144 * 144];
__device__ __align__(16) __half g_whi[1769472];
__device__ __align__(16) __half g_wlo[1769472];

__device__ __forceinline__ int win_src_row(int m) {
    int wi = m / kN, t = m - wi * kN;
    int b  = wi >> 4;
    int wh = (wi >> 2) & 3;
    int ww = wi & 3;
    int th = t / kWS, tw = t - th * kWS;
    int sh = wh * kWS + th + kSHIFT; if (sh >= kH) sh -= kH;
    int sw = ww * kWS + tw + kSHIFT; if (sw >= kW) sw -= kW;
    return (b * kH + sh) * kW + sw;
}

__device__ __forceinline__ uint32_t smem_u32(const void* p) {
    uint32_t a;
    asm("{ .reg .u64 t; cvta.to.shared.u64 t, %1; cvt.u32.u64 %0, t; }" : "=r"(a) : "l"(p));
    return a;
}
__device__ __forceinline__ void mma16(float* c, const uint32_t* a, const uint32_t* b) {
    asm volatile("mma.sync.aligned.m16n8k16.row.col.f32.f16.f16.f32 "
        "{%0,%1,%2,%3},{%4,%5,%6,%7},{%8,%9},{%0,%1,%2,%3};"
        : "+f"(c[0]), "+f"(c[1]), "+f"(c[2]), "+f"(c[3])
        : "r"(a[0]), "r"(a[1]), "r"(a[2]), "r"(a[3]), "r"(b[0]), "r"(b[1]));
}
__device__ __forceinline__ void cpa16(uint32_t dst, const void* src) {
    asm volatile("cp.async.ca.shared.global [%0], [%1], 16;" :: "r"(dst), "l"(src));
}
__device__ __forceinline__ void cpa_commit() {
    asm volatile("cp.async.commit_group;" ::: "memory");
}
template <int Nw>
__device__ __forceinline__ void cpa_wait() {
    asm volatile("cp.async.wait_group %0;" :: "n"(Nw) : "memory");
}
__device__ __forceinline__ void split_h(float v, __half& h, __half& l) {
    h = __float2half_rn(v);
    l = __float2half_rn(v - __half2float(h));
}

// ---------------------------------------------------------------------------
// K0a: weight transpose + fp16 hi/lo split.  W[K][N] -> hi/lo[n][k]
// ---------------------------------------------------------------------------
__global__ void wsplit_kernel(const float* __restrict__ W,
                              __half* __restrict__ hi, __half* __restrict__ lo,
                              int K, int N) {
    long idx = (long)blockIdx.x * 256 + threadIdx.x;
    if (idx >= (long)K * N) return;
    int n = (int)(idx / K), k = (int)(idx % K);
    float v = W[(long)k * N + n];
    __half h, l; split_h(v, h, l);
    hi[idx] = h; lo[idx] = l;
}

// K0b: activation split (same layout)
__global__ void xsplit_kernel(const float* __restrict__ X,
                              __half* __restrict__ hi, __half* __restrict__ lo,
                              long n) {
    long i = (long)blockIdx.x * 256 + threadIdx.x;
    if (i >= n) return;
    __half h, l; split_h(X[i], h, l);
    hi[i] = h; lo[i] = l;
}

// ---------------------------------------------------------------------------
// K1: CPB MLP -> 16*sigmoid table; K1b: expand + fold mask
// ---------------------------------------------------------------------------
__global__ void cpb_kernel(const float* __restrict__ table,
                           const float* __restrict__ w1,
                           const float* __restrict__ b1,
                           const float* __restrict__ w2) {
    __shared__ float hid[512];
    int e = blockIdx.x;
    int tid = threadIdx.x;
    float t0 = table[e * 2 + 0], t1 = table[e * 2 + 1];
    hid[tid] = fmaxf(0.f, fmaf(t0, w1[tid], fmaf(t1, w1[512 + tid], b1[tid])));
    __syncthreads();
    if (tid < 12) {
        float s = 0.f;
        #pragma unroll 8
        for (int i = 0; i < 512; i++) s = fmaf(hid[i], w2[i * 12 + tid], s);
        g_btab[e * 12 + tid] = 16.f / (1.f + expf(-s));
    }
}

__global__ void bias_expand_kernel(const int* __restrict__ rpi,
                                   const float* __restrict__ mask) {
    int idx = blockIdx.x * 256 + threadIdx.x;
    if (idx >= 16 * 12 * 144 * 144) return;
    int rj = idx % (144 * 144);
    int wh = idx / (144 * 144);
    int h = wh % 12, wt = wh / 12;
    g_bias2[idx] = g_btab[rpi[rj] * 12 + h] + mask[wt * 144 * 144 + rj];
}

// ---------------------------------------------------------------------------
// fp16 3-term GEMM: 128x128 tile, BK=32, 2-stage cp.async, 256 threads,
// 8 warps each 32x64 via mma.m16n8k16.  D = AhiBhi + AhiBlo + AloBhi.
// MODE 0: qkv (A gathered; scatter epilogue, f32 out + q/v bias)
// MODE 1: bias, f32 out
// MODE 2: bias + exact GELU, fp16 hi/lo out
// ---------------------------------------------------------------------------
template <int MODE, int Ncols, int Kdim>
__global__ void __launch_bounds__(256, 2) gemm_h3(
    const __half* __restrict__ Ahi_g, const __half* __restrict__ Alo_g,
    const __half* __restrict__ Bhi_g, const __half* __restrict__ Blo_g,
    const float* __restrict__ bias, const float* __restrict__ bias2,
    float* __restrict__ CoutF, __half* __restrict__ CHhi, __half* __restrict__ CHlo) {
    extern __shared__ uint32_t smw[];
    uint32_t sb = smem_u32(smw);

    int tid = threadIdx.x;
    int bx = blockIdx.x, by = blockIdx.y;
    int warp = tid >> 5, lane = tid & 31;
    int g = lane >> 2, t = lane & 3;
    int wm = (warp & 3) * 32, wn = (warp >> 2) * 64;
    constexpr int NCHUNK = Kdim / 32;

    // per-thread load map: 2 rows (r, r+64), seg = 16B chunk of 8 halves
    int lrow = tid >> 2, seg = tid & 3;
    long arows[2];
    #pragma unroll
    for (int i = 0; i < 2; i++) {
        int gr = by * 128 + lrow + 64 * i;
        arows[i] = (MODE == 0) ? (long)win_src_row(gr) : (long)gr;
    }
    long brows[2];
    #pragma unroll
    for (int i = 0; i < 2; i++) brows[i] = bx * 128 + lrow + 64 * i;

    auto load_stage = [&](int s, int kc) {
        uint32_t stb = sb + s * (STAGEW * 4);
        #pragma unroll
        for (int i = 0; i < 2; i++) {
            int row = lrow + 64 * i;
            uint32_t d = stb + row * (ST2 * 4) + seg * 16;
            cpa16(d,                Ahi_g + arows[i] * Kdim + kc + seg * 8);
            cpa16(d + BUFW * 4,     Alo_g + arows[i] * Kdim + kc + seg * 8);
            cpa16(d + 2 * BUFW * 4, Bhi_g + brows[i] * Kdim + kc + seg * 8);
            cpa16(d + 3 * BUFW * 4, Blo_g + brows[i] * Kdim + kc + seg * 8);
        }
    };

    float acc[2][8][4];
    #pragma unroll
    for (int i = 0; i < 2; i++)
        #pragma unroll
        for (int j = 0; j < 8; j++)
            #pragma unroll
            for (int q = 0; q < 4; q++) acc[i][j][q] = 0.f;

    load_stage(0, 0);
    cpa_commit();

    for (int c = 0; c < NCHUNK; c++) {
        if (c + 1 < NCHUNK) load_stage((c + 1) & 1, (c + 1) * 32);
        cpa_commit();
        cpa_wait<1>();
        __syncthreads();
        const uint32_t* Ah = smw + (c & 1) * STAGEW;
        const uint32_t* Al = Ah + BUFW;
        const uint32_t* Bh = Ah + 2 * BUFW;
        const uint32_t* Bl = Ah + 3 * BUFW;
        #pragma unroll
        for (int kk = 0; kk < 2; kk++) {      // two k16 steps
            int k0 = kk * 8;                  // word offset
            uint32_t ah[2][4], al[2][4];
            #pragma unroll
            for (int mt = 0; mt < 2; mt++) {
                int r0 = (wm + mt * 16 + g) * ST2 + k0 + t;
                int r8 = r0 + 8 * ST2;
                ah[mt][0] = Ah[r0];     ah[mt][1] = Ah[r8];
                ah[mt][2] = Ah[r0 + 4]; ah[mt][3] = Ah[r8 + 4];
                al[mt][0] = Al[r0];     al[mt][1] = Al[r8];
                al[mt][2] = Al[r0 + 4]; al[mt][3] = Al[r8 + 4];
            }
            #pragma unroll
            for (int nt = 0; nt < 8; nt++) {
                int nb = (wn + nt * 8 + g) * ST2 + k0 + t;
                uint32_t bh[2] = { Bh[nb], Bh[nb + 4] };
                uint32_t bl[2] = { Bl[nb], Bl[nb + 4] };
                #pragma unroll
                for (int mt = 0; mt < 2; mt++) {
                    mma16(acc[mt][nt], ah[mt], bh);
                    mma16(acc[mt][nt], ah[mt], bl);
                    mma16(acc[mt][nt], al[mt], bh);
                }
            }
        }
        __syncthreads();
    }

    // ---- epilogue ----
    int gr = by * 128 + wm + g;
    int gc = bx * 128 + wn + 2 * t;
    #pragma unroll
    for (int mt = 0; mt < 2; mt++) {
        int r0 = gr + mt * 16;
        #pragma unroll
        for (int nt = 0; nt < 8; nt++) {
            int c0 = gc + nt * 8;
            if (MODE == 0) {
                #pragma unroll
                for (int e = 0; e < 4; e++) {
                    int row = r0 + (e >> 1) * 8;
                    int col = c0 + (e & 1);
                    int wi = row / kN, tk = row - wi * kN;
                    int part = col / kC, cc = col - part * kC;
                    float bv = (part == 0) ? bias[cc] : (part == 2 ? bias2[cc] : 0.f);
                    g_scratch[(long)part * kSLOT +
                              (((long)(wi * kNH + (cc >> 5))) * kN + tk) * kHD + (cc & 31)]
                        = acc[mt][nt][e] + bv;
                }
            } else if (MODE == 1) {
                float b0 = bias[c0], b1 = bias[c0 + 1];
                float2 v;
                v.x = acc[mt][nt][0] + b0; v.y = acc[mt][nt][1] + b1;
                *(float2*)&CoutF[(long)r0 * Ncols + c0] = v;
                v.x = acc[mt][nt][2] + b0; v.y = acc[mt][nt][3] + b1;
                *(float2*)&CoutF[(long)(r0 + 8) * Ncols + c0] = v;
            } else {
                float b0 = bias[c0], b1 = bias[c0 + 1];
                #pragma unroll
                for (int half_ = 0; half_ < 2; half_++) {
                    float vx = acc[mt][nt][2 * half_ + 0] + b0;
                    float vy = acc[mt][nt][2 * half_ + 1] + b1;
                    vx = 0.5f * vx * (1.f + erff(vx * 0.70710678f));
                    vy = 0.5f * vy * (1.f + erff(vy * 0.70710678f));
                    __half hx, lx, hy, ly;
                    split_h(vx, hx, lx);
                    split_h(vy, hy, ly);
                    long off = (long)(r0 + 8 * half_) * Ncols + c0;
                    *(__half2*)(CHhi + off) = __halves2half2(hx, hy);
                    *(__half2*)(CHlo + off) = __halves2half2(lx, ly);
                }
            }
        }
    }
}

// ---------------------------------------------------------------------------
// K3: cosine attention, one block per (window, head). 160 threads, 1 row each.
// Fixed stabilizer mx = scale + 16.  Output: fp16 hi/lo (proj operand).
// ---------------------------------------------------------------------------
__global__ void __launch_bounds__(160) attn_kernel(const float* __restrict__ lsc,
                                                   __half* __restrict__ Ohi,
                                                   __half* __restrict__ Olo) {
    __shared__ float4 ks4[144 * 8];
    __shared__ float4 vs4[144 * 8];
    int bh = blockIdx.x;
    int wi = bh / kNH, h = bh - wi * kNH;
    int tid = threadIdx.x;

    const float4* qg = (const float4*)(g_scratch + 0 * kSLOT + (long)bh * kN * kHD);
    const float4* kg = (const float4*)(g_scratch + 1 * kSLOT + (long)bh * kN * kHD);
    const float4* vg = (const float4*)(g_scratch + 2 * kSLOT + (long)bh * kN * kHD);

    for (int i = tid; i < 144 * 8; i += 160) {
        ks4[i] = kg[i];
        vs4[i] = vg[i];
    }
    __syncthreads();
    if (tid < kN) {
        float s = 0.f;
        float4 kr[8];
        #pragma unroll
        for (int d = 0; d < 8; d++) {
            kr[d] = ks4[tid * 8 + d];
            s += kr[d].x * kr[d].x + kr[d].y * kr[d].y + kr[d].z * kr[d].z + kr[d].w * kr[d].w;
        }
        float inv = 1.f / fmaxf(sqrtf(s), 1e-12f);
        #pragma unroll
        for (int d = 0; d < 8; d++) {
            kr[d].x *= inv; kr[d].y *= inv; kr[d].z *= inv; kr[d].w *= inv;
            ks4[tid * 8 + d] = kr[d];
        }
    }
    __syncthreads();

    if (tid < kN) {
        int r = tid;
        float scale = __expf(fminf(lsc[h], 4.605170185988092f));
        float4 qr[8];
        float s = 0.f;
        #pragma unroll
        for (int d = 0; d < 8; d++) {
            qr[d] = qg[r * 8 + d];
            s += qr[d].x * qr[d].x + qr[d].y * qr[d].y + qr[d].z * qr[d].z + qr[d].w * qr[d].w;
        }
        float inv = scale / fmaxf(sqrtf(s), 1e-12f);
        #pragma unroll
        for (int d = 0; d < 8; d++) {
            qr[d].x *= inv; qr[d].y *= inv; qr[d].z *= inv; qr[d].w *= inv;
        }

        const float* comb = g_bias2 + ((long)((wi & 15) * kNH + h) * kN + r) * kN;
        float mx = scale + 16.f;
        float4 o[8];
        #pragma unroll
        for (int d = 0; d < 8; d++) o[d] = make_float4(0.f, 0.f, 0.f, 0.f);
        float sum = 0.f;
        for (int j = 0; j < kN; j++) {
            float tt = comb[j];
            #pragma unroll
            for (int d = 0; d < 8; d++) {
                float4 kv = ks4[j * 8 + d];
                tt = fmaf(qr[d].x, kv.x, tt);
                tt = fmaf(qr[d].y, kv.y, tt);
                tt = fmaf(qr[d].z, kv.z, tt);
                tt = fmaf(qr[d].w, kv.w, tt);
            }
            float e = __expf(tt - mx);
            sum += e;
            #pragma unroll
            for (int d = 0; d < 8; d++) {
                float4 vv = vs4[j * 8 + d];
                o[d].x = fmaf(e, vv.x, o[d].x);
                o[d].y = fmaf(e, vv.y, o[d].y);
                o[d].z = fmaf(e, vv.z, o[d].z);
                o[d].w = fmaf(e, vv.w, o[d].w);
            }
        }
        float rs = 1.f / sum;
        long obase = (long)(wi * kN + r) * kC + h * kHD;
        #pragma unroll
        for (int d = 0; d < 8; d++) {
            float ox = o[d].x * rs, oy = o[d].y * rs, oz = o[d].z * rs, ow = o[d].w * rs;
            __half hx, lx, hy, ly, hz, lz, hw, lw;
            split_h(ox, hx, lx); split_h(oy, hy, ly);
            split_h(oz, hz, lz); split_h(ow, hw, lw);
            *(__half2*)(Ohi + obase + 4 * d)     = __halves2half2(hx, hy);
            *(__half2*)(Ohi + obase + 4 * d + 2) = __halves2half2(hz, hw);
            *(__half2*)(Olo + obase + 4 * d)     = __halves2half2(lx, ly);
            *(__half2*)(Olo + obase + 4 * d + 2) = __halves2half2(lz, lw);
        }
    }
}

// ---------------------------------------------------------------------------
// LN + residual. SCATTER: window->image reorder + emit fp16 hi/lo split.
// ---------------------------------------------------------------------------
template <bool SCATTER>
__global__ void __launch_bounds__(128) ln_res_kernel(
    const float* __restrict__ src, const float* __restrict__ resid,
    const float* __restrict__ gam, const float* __restrict__ bet,
    float* __restrict__ out, __half* __restrict__ Shi, __half* __restrict__ Slo) {
    int m = blockIdx.x;
    int dst = SCATTER ? win_src_row(m) : m;
    const float* row = src + (long)m * kC;
    int tid = threadIdx.x;
    float v0 = row[tid], v1 = row[tid + 128], v2 = row[tid + 256];
    float s = v0 + v1 + v2;
    float s2 = v0 * v0 + v1 * v1 + v2 * v2;
    #pragma unroll
    for (int o = 16; o > 0; o >>= 1) {
        s  += __shfl_xor_sync(0xffffffffu, s, o);
        s2 += __shfl_xor_sync(0xffffffffu, s2, o);
    }
    __shared__ float sh[8];
    int wid = tid >> 5, lane = tid & 31;
    if (lane == 0) { sh[wid] = s; sh[4 + wid] = s2; }
    __syncthreads();
    s  = sh[0] + sh[1] + sh[2] + sh[3];
    s2 = sh[4] + sh[5] + sh[6] + sh[7];
    float mean = s * (1.f / 384.f);
    float var = s2 * (1.f / 384.f) - mean * mean;
    float rstd = rsqrtf(var + 1e-5f);
    const float* rrow = resid + (long)dst * kC;
    float* orow = out + (long)dst * kC;
    #pragma unroll
    for (int q = 0; q < 3; q++) {
        int col = tid + 128 * q;
        float v = (q == 0 ? v0 : (q == 1 ? v1 : v2));
        float y = rrow[col] + (v - mean) * rstd * gam[col] + bet[col];
        orow[col] = y;
        if (SCATTER) {
            __half h, l; split_h(y, h, l);
            Shi[(long)dst * kC + col] = h;
            Slo[(long)dst * kC + col] = l;
        }
    }
}

// ---------------------------------------------------------------------------
extern "C" void kernel_launch(void* const* d_in, const int* in_sizes, int n_in,
                              void* d_out, int out_size) {
    const float* x    = (const float*)d_in[0];
    const float* tab  = (const float*)d_in[1];
    const int*   rpi  = (const int*)  d_in[2];
    const float* mask = (const float*)d_in[3];
    const float* qkvw = (const float*)d_in[4];
    const float* qb   = (const float*)d_in[5];
    const float* vb   = (const float*)d_in[6];
    const float* lsc  = (const float*)d_in[7];
    const float* w1   = (const float*)d_in[8];
    const float* b1   = (const float*)d_in[9];
    const float* w2   = (const float*)d_in[10];
    const float* pw   = (const float*)d_in[11];
    const float* pb   = (const float*)d_in[12];
    const float* n1g  = (const float*)d_in[13];
    const float* n1b  = (const float*)d_in[14];
    const float* n2g  = (const float*)d_in[15];
    const float* n2b  = (const float*)d_in[16];
    const float* f1w  = (const float*)d_in[17];
    const float* f1b  = (const float*)d_in[18];
    const float* f2w  = (const float*)d_in[19];
    const float* f2b  = (const float*)d_in[20];
    float* out = (float*)d_out;

    float* f = nullptr;
    cudaGetSymbolAddress((void**)&f, g_scratch);
    __half* whi = nullptr; cudaGetSymbolAddress((void**)&whi, g_whi);
    __half* wlo = nullptr; cudaGetSymbolAddress((void**)&wlo, g_wlo);

    // scratch buffer map
    __half* attn_hi = (__half*)(f + 3 * kSLOT);
    __half* attn_lo = attn_hi + kSLOT;
    __half* x_hi    = (__half*)(f + 4 * kSLOT);   // reused as x1 split
    __half* x_lo    = x_hi + kSLOT;
    float*  proj_f  = f + 5 * kSLOT;
    float*  x1_f    = f + 1 * kSLOT;
    __half* h_hi    = (__half*)(f + 2 * kSLOT);   // spans s2,s3
    __half* h_lo    = (__half*)(f + 5 * kSLOT);   // spans s5,s6
    float*  y_f     = f + 7 * kSLOT;

    cudaFuncSetAttribute(gemm_h3<0, 1152, 384>, cudaFuncAttributeMaxDynamicSharedMemorySize, SMEM_DYN);
    cudaFuncSetAttribute(gemm_h3<1, 384, 384>,  cudaFuncAttributeMaxDynamicSharedMemorySize, SMEM_DYN);
    cudaFuncSetAttribute(gemm_h3<2, 1536, 384>, cudaFuncAttributeMaxDynamicSharedMemorySize, SMEM_DYN);
    cudaFuncSetAttribute(gemm_h3<1, 384, 1536>, cudaFuncAttributeMaxDynamicSharedMemorySize, SMEM_DYN);

    // 0. weight splits (transposed [n][k]) + x split
    wsplit_kernel<<<(442368 + 255) / 256, 256>>>(qkvw, whi + OQKV, wlo + OQKV, 384, 1152);
    wsplit_kernel<<<(147456 + 255) / 256, 256>>>(pw,  whi + OPROJ, wlo + OPROJ, 384, 384);
    wsplit_kernel<<<(589824 + 255) / 256, 256>>>(f1w, whi + OFC1,  wlo + OFC1,  384, 1536);
    wsplit_kernel<<<(589824 + 255) / 256, 256>>>(f2w, whi + OFC2,  wlo + OFC2,  1536, 384);
    xsplit_kernel<<<(int)((kSLOT + 255) / 256), 256>>>(x, x_hi, x_lo, kSLOT);

    // 1. CPB bias table + expansion (bias + mask combined)
    cpb_kernel<<<529, 512>>>(tab, w1, b1, w2);
    bias_expand_kernel<<<(16 * 12 * 144 * 144 + 255) / 256, 256>>>(rpi, mask);

    // 2. QKV GEMM (gathered A) -> q/k/v f32 slots
    gemm_h3<0, 1152, 384><<<dim3(9, 576), 256, SMEM_DYN>>>(
        x_hi, x_lo, whi + OQKV, wlo + OQKV, qb, vb, nullptr, nullptr, nullptr);

    // 3. attention -> attn hi/lo
    attn_kernel<<<512 * kNH, 160>>>(lsc, attn_hi, attn_lo);

    // 4. proj GEMM -> proj_f
    gemm_h3<1, 384, 384><<<dim3(3, 576), 256, SMEM_DYN>>>(
        attn_hi, attn_lo, whi + OPROJ, wlo + OPROJ, pb, nullptr, proj_f, nullptr, nullptr);

    // 5. LN1 + residual + scatter -> x1_f + x1 split (into x_hi/x_lo)
    ln_res_kernel<true><<<kM, 128>>>(proj_f, x, n1g, n1b, x1_f, x_hi, x_lo);

    // 6. fc1 + GELU -> h hi/lo
    gemm_h3<2, 1536, 384><<<dim3(12, 576), 256, SMEM_DYN>>>(
        x_hi, x_lo, whi + OFC1, wlo + OFC1, f1b, nullptr, nullptr, h_hi, h_lo);

    // 7. fc2 -> y_f
    gemm_h3<1, 384, 1536><<<dim3(3, 576), 256, SMEM_DYN>>>(
        h_hi, h_lo, whi + OFC2, wlo + OFC2, f2b, nullptr, y_f, nullptr, nullptr);

    // 8. final LN + residual -> out
    ln_res_kernel<false><<<kM, 128>>>(y_f, x1_f, n2g, n2b, out, nullptr, nullptr);
}

// round 7
// speedup vs baseline: 1.4631x; 1.4631x over previous
#include <cuda_runtime.h>
#include <cuda_fp16.h>
#include <math.h>
#include <stdint.h>

// ---------------------------------------------------------------------------
// SwinV2 block: B=32, H=W=48, C=384, NH=12, WS=12, N=144, SHIFT=6
// GEMMs: single-term fp16 mma.m16n8k16 (fp32 accum), cp.async 2-stage.
// (fp16 mantissa == tf32 mantissa == 10 bits; measured e2e rel_err ~5.6e-4)
// ---------------------------------------------------------------------------
namespace {
constexpr int kH = 48;
constexpr int kW = 48;
constexpr int kC = 384;
constexpr int kNH = 12;
constexpr int kHD = 32;
constexpr int kWS = 12;
constexpr int kN = 144;
constexpr int kSHIFT = 6;
constexpr int kM = 73728;        // 512 windows * 144 tokens
constexpr long kSLOT = 28311552; // kM * kC elements

constexpr int ST2 = 20;          // smem row stride in 32-bit words (40 halves)
constexpr int BUFW = 128 * ST2;  // words per operand buffer (2560)
constexpr int STAGEW = 2 * BUFW; // A | B per stage (5120 words)
constexpr int SMEM_DYN = 2 * STAGEW * 4;  // 40960 B

// fp16 weight offsets (halves), [n][k] layout
constexpr long OQKV = 0;        // 1152 x 384
constexpr long OPROJ = 442368;  // 384 x 384
constexpr long OFC1 = 589824;   // 1536 x 384
constexpr long OFC2 = 1179648;  // 384 x 1536
}

// scratch slots (28311552 f32 each):
// s0 q | s1 k -> x1 f32 | s2 v -> h_h(spans s2,s3) | s3 attn_h
// s4 x_h -> x1_h | s5 proj_f | s7 y_f
__device__ float g_scratch[8 * 28311552ULL];
__device__ float g_btab[529 * 12];
__device__ float g_bias2[16 * 12 * 144 * 144];
__device__ __align__(16) __half g_whi[1769472];

__device__ __forceinline__ int win_src_row(int m) {
    int wi = m / kN, t = m - wi * kN;
    int b  = wi >> 4;
    int wh = (wi >> 2) & 3;
    int ww = wi & 3;
    int th = t / kWS, tw = t - th * kWS;
    int sh = wh * kWS + th + kSHIFT; if (sh >= kH) sh -= kH;
    int sw = ww * kWS + tw + kSHIFT; if (sw >= kW) sw -= kW;
    return (b * kH + sh) * kW + sw;
}

__device__ __forceinline__ uint32_t smem_u32(const void* p) {
    uint32_t a;
    asm("{ .reg .u64 t; cvta.to.shared.u64 t, %1; cvt.u32.u64 %0, t; }" : "=r"(a) : "l"(p));
    return a;
}
__device__ __forceinline__ void mma16(float* c, const uint32_t* a, const uint32_t* b) {
    asm volatile("mma.sync.aligned.m16n8k16.row.col.f32.f16.f16.f32 "
        "{%0,%1,%2,%3},{%4,%5,%6,%7},{%8,%9},{%0,%1,%2,%3};"
        : "+f"(c[0]), "+f"(c[1]), "+f"(c[2]), "+f"(c[3])
        : "r"(a[0]), "r"(a[1]), "r"(a[2]), "r"(a[3]), "r"(b[0]), "r"(b[1]));
}
__device__ __forceinline__ void cpa16(uint32_t dst, const void* src) {
    asm volatile("cp.async.ca.shared.global [%0], [%1], 16;" :: "r"(dst), "l"(src));
}
__device__ __forceinline__ void cpa_commit() {
    asm volatile("cp.async.commit_group;" ::: "memory");
}
template <int Nw>
__device__ __forceinline__ void cpa_wait() {
    asm volatile("cp.async.wait_group %0;" :: "n"(Nw) : "memory");
}

// ---------------------------------------------------------------------------
// K0a: weight transpose to fp16.  W[K][N] -> hi[n][k]
// ---------------------------------------------------------------------------
__global__ void wsplit_kernel(const float* __restrict__ W,
                              __half* __restrict__ hi, int K, int N) {
    long idx = (long)blockIdx.x * 256 + threadIdx.x;
    if (idx >= (long)K * N) return;
    int n = (int)(idx / K), k = (int)(idx % K);
    hi[idx] = __float2half_rn(W[(long)k * N + n]);
}

// K0b: activation convert
__global__ void xsplit_kernel(const float* __restrict__ X,
                              __half* __restrict__ hi, long n) {
    long i = (long)blockIdx.x * 256 + threadIdx.x;
    if (i < n) hi[i] = __float2half_rn(X[i]);
}

// ---------------------------------------------------------------------------
// K1: CPB MLP -> 16*sigmoid table; K1b: expand + fold mask
// ---------------------------------------------------------------------------
__global__ void cpb_kernel(const float* __restrict__ table,
                           const float* __restrict__ w1,
                           const float* __restrict__ b1,
                           const float* __restrict__ w2) {
    __shared__ float hid[512];
    int e = blockIdx.x;
    int tid = threadIdx.x;
    float t0 = table[e * 2 + 0], t1 = table[e * 2 + 1];
    hid[tid] = fmaxf(0.f, fmaf(t0, w1[tid], fmaf(t1, w1[512 + tid], b1[tid])));
    __syncthreads();
    if (tid < 12) {
        float s = 0.f;
        #pragma unroll 8
        for (int i = 0; i < 512; i++) s = fmaf(hid[i], w2[i * 12 + tid], s);
        g_btab[e * 12 + tid] = 16.f / (1.f + expf(-s));
    }
}

__global__ void bias_expand_kernel(const int* __restrict__ rpi,
                                   const float* __restrict__ mask) {
    int idx = blockIdx.x * 256 + threadIdx.x;
    if (idx >= 16 * 12 * 144 * 144) return;
    int rj = idx % (144 * 144);
    int wh = idx / (144 * 144);
    int h = wh % 12, wt = wh / 12;
    g_bias2[idx] = g_btab[rpi[rj] * 12 + h] + mask[wt * 144 * 144 + rj];
}

// ---------------------------------------------------------------------------
// fp16 single-term GEMM: 128x128 tile, BK=32, 2-stage cp.async, 256 threads,
// 8 warps each 32x64 via mma.m16n8k16.
// MODE 0: qkv (A gathered; scatter epilogue, f32 out + q/v bias)
// MODE 1: bias, f32 out
// MODE 2: bias + exact GELU, fp16 out
// ---------------------------------------------------------------------------
template <int MODE, int Ncols, int Kdim>
__global__ void __launch_bounds__(256, 2) gemm_h1(
    const __half* __restrict__ A_g, const __half* __restrict__ B_g,
    const float* __restrict__ bias, const float* __restrict__ bias2,
    float* __restrict__ CoutF, __half* __restrict__ CoutH) {
    extern __shared__ uint32_t smw[];
    uint32_t sb = smem_u32(smw);

    int tid = threadIdx.x;
    int bx = blockIdx.x, by = blockIdx.y;
    int warp = tid >> 5, lane = tid & 31;
    int g = lane >> 2, t = lane & 3;
    int wm = (warp & 3) * 32, wn = (warp >> 2) * 64;
    constexpr int NCHUNK = Kdim / 32;

    // load map: each thread copies 2 chunks of A and 2 of B (16B each).
    // row = tid>>1 (0..127), chunk pair seg2 = (tid&1)*2 + {0,1}
    int lrow = tid >> 1;
    int segb = (tid & 1) * 2;
    long arow;
    {
        int gr = by * 128 + lrow;
        arow = (MODE == 0) ? (long)win_src_row(gr) : (long)gr;
    }
    long brow = bx * 128 + lrow;

    auto load_stage = [&](int s, int kc) {
        uint32_t stb = sb + s * (STAGEW * 4);
        uint32_t da = stb + lrow * (ST2 * 4) + segb * 16;
        uint32_t db = da + BUFW * 4;
        const __half* ga = A_g + arow * Kdim + kc + segb * 8;
        const __half* gb = B_g + brow * Kdim + kc + segb * 8;
        cpa16(da,      ga);
        cpa16(da + 16, ga + 8);
        cpa16(db,      gb);
        cpa16(db + 16, gb + 8);
    };

    float acc[2][8][4];
    #pragma unroll
    for (int i = 0; i < 2; i++)
        #pragma unroll
        for (int j = 0; j < 8; j++)
            #pragma unroll
            for (int q = 0; q < 4; q++) acc[i][j][q] = 0.f;

    load_stage(0, 0);
    cpa_commit();

    for (int c = 0; c < NCHUNK; c++) {
        if (c + 1 < NCHUNK) load_stage((c + 1) & 1, (c + 1) * 32);
        cpa_commit();
        cpa_wait<1>();
        __syncthreads();
        const uint32_t* Ah = smw + (c & 1) * STAGEW;
        const uint32_t* Bh = Ah + BUFW;
        #pragma unroll
        for (int kk = 0; kk < 2; kk++) {      // two k16 steps
            int k0 = kk * 8;                  // word offset
            uint32_t ah[2][4];
            #pragma unroll
            for (int mt = 0; mt < 2; mt++) {
                int r0 = (wm + mt * 16 + g) * ST2 + k0 + t;
                int r8 = r0 + 8 * ST2;
                ah[mt][0] = Ah[r0];     ah[mt][1] = Ah[r8];
                ah[mt][2] = Ah[r0 + 4]; ah[mt][3] = Ah[r8 + 4];
            }
            #pragma unroll
            for (int nt = 0; nt < 8; nt++) {
                int nb = (wn + nt * 8 + g) * ST2 + k0 + t;
                uint32_t bh[2] = { Bh[nb], Bh[nb + 4] };
                #pragma unroll
                for (int mt = 0; mt < 2; mt++)
                    mma16(acc[mt][nt], ah[mt], bh);
            }
        }
        __syncthreads();
    }

    // ---- epilogue ----
    int gr = by * 128 + wm + g;
    int gc = bx * 128 + wn + 2 * t;
    #pragma unroll
    for (int mt = 0; mt < 2; mt++) {
        int r0 = gr + mt * 16;
        #pragma unroll
        for (int nt = 0; nt < 8; nt++) {
            int c0 = gc + nt * 8;
            if (MODE == 0) {
                #pragma unroll
                for (int e = 0; e < 4; e++) {
                    int row = r0 + (e >> 1) * 8;
                    int col = c0 + (e & 1);
                    int wi = row / kN, tk = row - wi * kN;
                    int part = col / kC, cc = col - part * kC;
                    float bv = (part == 0) ? bias[cc] : (part == 2 ? bias2[cc] : 0.f);
                    g_scratch[(long)part * kSLOT +
                              (((long)(wi * kNH + (cc >> 5))) * kN + tk) * kHD + (cc & 31)]
                        = acc[mt][nt][e] + bv;
                }
            } else if (MODE == 1) {
                float b0 = bias[c0], b1 = bias[c0 + 1];
                float2 v;
                v.x = acc[mt][nt][0] + b0; v.y = acc[mt][nt][1] + b1;
                *(float2*)&CoutF[(long)r0 * Ncols + c0] = v;
                v.x = acc[mt][nt][2] + b0; v.y = acc[mt][nt][3] + b1;
                *(float2*)&CoutF[(long)(r0 + 8) * Ncols + c0] = v;
            } else {
                float b0 = bias[c0], b1 = bias[c0 + 1];
                #pragma unroll
                for (int hh = 0; hh < 2; hh++) {
                    float vx = acc[mt][nt][2 * hh + 0] + b0;
                    float vy = acc[mt][nt][2 * hh + 1] + b1;
                    vx = 0.5f * vx * (1.f + erff(vx * 0.70710678f));
                    vy = 0.5f * vy * (1.f + erff(vy * 0.70710678f));
                    long off = (long)(r0 + 8 * hh) * Ncols + c0;
                    *(__half2*)(CoutH + off) =
                        __halves2half2(__float2half_rn(vx), __float2half_rn(vy));
                }
            }
        }
    }
}

// ---------------------------------------------------------------------------
// K3: cosine attention, one block per (window, head). 160 threads, 1 row each.
// Fixed stabilizer mx = scale + 16.  Output: fp16 (proj operand).
// ---------------------------------------------------------------------------
__global__ void __launch_bounds__(160) attn_kernel(const float* __restrict__ lsc,
                                                   __half* __restrict__ Oh) {
    __shared__ float4 ks4[144 * 8];
    __shared__ float4 vs4[144 * 8];
    int bh = blockIdx.x;
    int wi = bh / kNH, h = bh - wi * kNH;
    int tid = threadIdx.x;

    const float4* qg = (const float4*)(g_scratch + 0 * kSLOT + (long)bh * kN * kHD);
    const float4* kg = (const float4*)(g_scratch + 1 * kSLOT + (long)bh * kN * kHD);
    const float4* vg = (const float4*)(g_scratch + 2 * kSLOT + (long)bh * kN * kHD);

    for (int i = tid; i < 144 * 8; i += 160) {
        ks4[i] = kg[i];
        vs4[i] = vg[i];
    }
    __syncthreads();
    if (tid < kN) {
        float s = 0.f;
        float4 kr[8];
        #pragma unroll
        for (int d = 0; d < 8; d++) {
            kr[d] = ks4[tid * 8 + d];
            s += kr[d].x * kr[d].x + kr[d].y * kr[d].y + kr[d].z * kr[d].z + kr[d].w * kr[d].w;
        }
        float inv = 1.f / fmaxf(sqrtf(s), 1e-12f);
        #pragma unroll
        for (int d = 0; d < 8; d++) {
            kr[d].x *= inv; kr[d].y *= inv; kr[d].z *= inv; kr[d].w *= inv;
            ks4[tid * 8 + d] = kr[d];
        }
    }
    __syncthreads();

    if (tid < kN) {
        int r = tid;
        float scale = __expf(fminf(lsc[h], 4.605170185988092f));
        float4 qr[8];
        float s = 0.f;
        #pragma unroll
        for (int d = 0; d < 8; d++) {
            qr[d] = qg[r * 8 + d];
            s += qr[d].x * qr[d].x + qr[d].y * qr[d].y + qr[d].z * qr[d].z + qr[d].w * qr[d].w;
        }
        float inv = scale / fmaxf(sqrtf(s), 1e-12f);
        #pragma unroll
        for (int d = 0; d < 8; d++) {
            qr[d].x *= inv; qr[d].y *= inv; qr[d].z *= inv; qr[d].w *= inv;
        }

        const float* comb = g_bias2 + ((long)((wi & 15) * kNH + h) * kN + r) * kN;
        float mx = scale + 16.f;
        float4 o[8];
        #pragma unroll
        for (int d = 0; d < 8; d++) o[d] = make_float4(0.f, 0.f, 0.f, 0.f);
        float sum = 0.f;
        for (int j = 0; j < kN; j++) {
            float tt = comb[j];
            #pragma unroll
            for (int d = 0; d < 8; d++) {
                float4 kv = ks4[j * 8 + d];
                tt = fmaf(qr[d].x, kv.x, tt);
                tt = fmaf(qr[d].y, kv.y, tt);
                tt = fmaf(qr[d].z, kv.z, tt);
                tt = fmaf(qr[d].w, kv.w, tt);
            }
            float e = __expf(tt - mx);
            sum += e;
            #pragma unroll
            for (int d = 0; d < 8; d++) {
                float4 vv = vs4[j * 8 + d];
                o[d].x = fmaf(e, vv.x, o[d].x);
                o[d].y = fmaf(e, vv.y, o[d].y);
                o[d].z = fmaf(e, vv.z, o[d].z);
                o[d].w = fmaf(e, vv.w, o[d].w);
            }
        }
        float rs = 1.f / sum;
        long obase = (long)(wi * kN + r) * kC + h * kHD;
        #pragma unroll
        for (int d = 0; d < 8; d++) {
            *(__half2*)(Oh + obase + 4 * d) =
                __halves2half2(__float2half_rn(o[d].x * rs), __float2half_rn(o[d].y * rs));
            *(__half2*)(Oh + obase + 4 * d + 2) =
                __halves2half2(__float2half_rn(o[d].z * rs), __float2half_rn(o[d].w * rs));
        }
    }
}

// ---------------------------------------------------------------------------
// LN + residual. SCATTER: window->image reorder + emit fp16 copy.
// ---------------------------------------------------------------------------
template <bool SCATTER>
__global__ void __launch_bounds__(128) ln_res_kernel(
    const float* __restrict__ src, const float* __restrict__ resid,
    const float* __restrict__ gam, const float* __restrict__ bet,
    float* __restrict__ out, __half* __restrict__ Sh) {
    int m = blockIdx.x;
    int dst = SCATTER ? win_src_row(m) : m;
    const float* row = src + (long)m * kC;
    int tid = threadIdx.x;
    float v0 = row[tid], v1 = row[tid + 128], v2 = row[tid + 256];
    float s = v0 + v1 + v2;
    float s2 = v0 * v0 + v1 * v1 + v2 * v2;
    #pragma unroll
    for (int o = 16; o > 0; o >>= 1) {
        s  += __shfl_xor_sync(0xffffffffu, s, o);
        s2 += __shfl_xor_sync(0xffffffffu, s2, o);
    }
    __shared__ float sh[8];
    int wid = tid >> 5, lane = tid & 31;
    if (lane == 0) { sh[wid] = s; sh[4 + wid] = s2; }
    __syncthreads();
    s  = sh[0] + sh[1] + sh[2] + sh[3];
    s2 = sh[4] + sh[5] + sh[6] + sh[7];
    float mean = s * (1.f / 384.f);
    float var = s2 * (1.f / 384.f) - mean * mean;
    float rstd = rsqrtf(var + 1e-5f);
    const float* rrow = resid + (long)dst * kC;
    float* orow = out + (long)dst * kC;
    #pragma unroll
    for (int q = 0; q < 3; q++) {
        int col = tid + 128 * q;
        float v = (q == 0 ? v0 : (q == 1 ? v1 : v2));
        float y = rrow[col] + (v - mean) * rstd * gam[col] + bet[col];
        orow[col] = y;
        if (SCATTER) Sh[(long)dst * kC + col] = __float2half_rn(y);
    }
}

// ---------------------------------------------------------------------------
extern "C" void kernel_launch(void* const* d_in, const int* in_sizes, int n_in,
                              void* d_out, int out_size) {
    const float* x    = (const float*)d_in[0];
    const float* tab  = (const float*)d_in[1];
    const int*   rpi  = (const int*)  d_in[2];
    const float* mask = (const float*)d_in[3];
    const float* qkvw = (const float*)d_in[4];
    const float* qb   = (const float*)d_in[5];
    const float* vb   = (const float*)d_in[6];
    const float* lsc  = (const float*)d_in[7];
    const float* w1   = (const float*)d_in[8];
    const float* b1   = (const float*)d_in[9];
    const float* w2   = (const float*)d_in[10];
    const float* pw   = (const float*)d_in[11];
    const float* pb   = (const float*)d_in[12];
    const float* n1g  = (const float*)d_in[13];
    const float* n1b  = (const float*)d_in[14];
    const float* n2g  = (const float*)d_in[15];
    const float* n2b  = (const float*)d_in[16];
    const float* f1w  = (const float*)d_in[17];
    const float* f1b  = (const float*)d_in[18];
    const float* f2w  = (const float*)d_in[19];
    const float* f2b  = (const float*)d_in[20];
    float* out = (float*)d_out;

    float* f = nullptr;
    cudaGetSymbolAddress((void**)&f, g_scratch);
    __half* whi = nullptr; cudaGetSymbolAddress((void**)&whi, g_whi);

    // scratch map
    __half* attn_h = (__half*)(f + 3 * kSLOT);
    __half* x_h    = (__half*)(f + 4 * kSLOT);   // reused as x1_h
    float*  proj_f = f + 5 * kSLOT;
    float*  x1_f   = f + 1 * kSLOT;
    __half* h_h    = (__half*)(f + 2 * kSLOT);   // kM x 1536 halves, spans s2,s3
    float*  y_f    = f + 7 * kSLOT;

    cudaFuncSetAttribute(gemm_h1<0, 1152, 384>, cudaFuncAttributeMaxDynamicSharedMemorySize, SMEM_DYN);
    cudaFuncSetAttribute(gemm_h1<1, 384, 384>,  cudaFuncAttributeMaxDynamicSharedMemorySize, SMEM_DYN);
    cudaFuncSetAttribute(gemm_h1<2, 1536, 384>, cudaFuncAttributeMaxDynamicSharedMemorySize, SMEM_DYN);
    cudaFuncSetAttribute(gemm_h1<1, 384, 1536>, cudaFuncAttributeMaxDynamicSharedMemorySize, SMEM_DYN);

    // 0. weight transposes (fp16 [n][k]) + x convert
    wsplit_kernel<<<(442368 + 255) / 256, 256>>>(qkvw, whi + OQKV, 384, 1152);
    wsplit_kernel<<<(147456 + 255) / 256, 256>>>(pw,  whi + OPROJ, 384, 384);
    wsplit_kernel<<<(589824 + 255) / 256, 256>>>(f1w, whi + OFC1,  384, 1536);
    wsplit_kernel<<<(589824 + 255) / 256, 256>>>(f2w, whi + OFC2,  1536, 384);
    xsplit_kernel<<<(int)((kSLOT + 255) / 256), 256>>>(x, x_h, kSLOT);

    // 1. CPB bias table + expansion (bias + mask combined)
    cpb_kernel<<<529, 512>>>(tab, w1, b1, w2);
    bias_expand_kernel<<<(16 * 12 * 144 * 144 + 255) / 256, 256>>>(rpi, mask);

    // 2. QKV GEMM (gathered A) -> q/k/v f32 slots
    gemm_h1<0, 1152, 384><<<dim3(9, 576), 256, SMEM_DYN>>>(
        x_h, whi + OQKV, qb, vb, nullptr, nullptr);

    // 3. attention -> attn_h
    attn_kernel<<<512 * kNH, 160>>>(lsc, attn_h);

    // 4. proj GEMM -> proj_f
    gemm_h1<1, 384, 384><<<dim3(3, 576), 256, SMEM_DYN>>>(
        attn_h, whi + OPROJ, pb, nullptr, proj_f, nullptr);

    // 5. LN1 + residual + scatter -> x1_f + x1_h
    ln_res_kernel<true><<<kM, 128>>>(proj_f, x, n1g, n1b, x1_f, x_h);

    // 6. fc1 + GELU -> h_h
    gemm_h1<2, 1536, 384><<<dim3(12, 576), 256, SMEM_DYN>>>(
        x_h, whi + OFC1, f1b, nullptr, nullptr, h_h);

    // 7. fc2 -> y_f
    gemm_h1<1, 384, 1536><<<dim3(3, 576), 256, SMEM_DYN>>>(
        h_h, whi + OFC2, f2b, nullptr, y_f, nullptr);

    // 8. final LN + residual -> out
    ln_res_kernel<false><<<kM, 128>>>(y_f, x1_f, n2g, n2b, out, nullptr);
}

// round 8
// speedup vs baseline: 1.6495x; 1.1274x over previous
#include <cuda_runtime.h>
#include <cuda_fp16.h>
#include <math.h>
#include <stdint.h>

// ---------------------------------------------------------------------------
// SwinV2 block: B=32, H=W=48, C=384, NH=12, WS=12, N=144, SHIFT=6
// GEMMs: fp16 mma.m16n8k16 (fp32 accum), cp.async 2-stage, ldmatrix frags.
// ---------------------------------------------------------------------------
namespace {
constexpr int kH = 48;
constexpr int kW = 48;
constexpr int kC = 384;
constexpr int kNH = 12;
constexpr int kHD = 32;
constexpr int kWS = 12;
constexpr int kN = 144;
constexpr int kSHIFT = 6;
constexpr int kM = 73728;        // 512 windows * 144 tokens
constexpr long kSLOT = 28311552; // kM * kC elements

constexpr int ST2 = 20;          // smem row stride in 32-bit words (40 halves)
constexpr int BUFW = 128 * ST2;  // words per operand buffer (2560)
constexpr int STAGEW = 2 * BUFW; // A | B per stage (5120 words)
constexpr int SMEM_DYN = 2 * STAGEW * 4;  // 40960 B

// fp16 weight offsets (halves), [n][k] layout
constexpr long OQKV = 0;        // 1152 x 384
constexpr long OPROJ = 442368;  // 384 x 384
constexpr long OFC1 = 589824;   // 1536 x 384
constexpr long OFC2 = 1179648;  // 384 x 1536
}

// scratch slots (28311552 f32 each):
// s0 q | s1 k -> x1 f32 | s2 v -> h_h(spans s2,s3) | s3 attn_h
// s4 x_h -> x1_h | s5 proj_f | s7 y_f
__device__ float g_scratch[8 * 28311552ULL];
__device__ float g_btab[529 * 12];
__device__ float g_bias2[16 * 12 * 144 * 144];
__device__ __align__(16) __half g_whi[1769472];

__device__ __forceinline__ int win_src_row(int m) {
    int wi = m / kN, t = m - wi * kN;
    int b  = wi >> 4;
    int wh = (wi >> 2) & 3;
    int ww = wi & 3;
    int th = t / kWS, tw = t - th * kWS;
    int sh = wh * kWS + th + kSHIFT; if (sh >= kH) sh -= kH;
    int sw = ww * kWS + tw + kSHIFT; if (sw >= kW) sw -= kW;
    return (b * kH + sh) * kW + sw;
}

__device__ __forceinline__ uint32_t smem_u32(const void* p) {
    uint32_t a;
    asm("{ .reg .u64 t; cvta.to.shared.u64 t, %1; cvt.u32.u64 %0, t; }" : "=r"(a) : "l"(p));
    return a;
}
__device__ __forceinline__ void mma16(float* c, const uint32_t* a, const uint32_t* b) {
    asm volatile("mma.sync.aligned.m16n8k16.row.col.f32.f16.f16.f32 "
        "{%0,%1,%2,%3},{%4,%5,%6,%7},{%8,%9},{%0,%1,%2,%3};"
        : "+f"(c[0]), "+f"(c[1]), "+f"(c[2]), "+f"(c[3])
        : "r"(a[0]), "r"(a[1]), "r"(a[2]), "r"(a[3]), "r"(b[0]), "r"(b[1]));
}
__device__ __forceinline__ void ldsm_x4(uint32_t* r, uint32_t addr) {
    asm volatile("ldmatrix.sync.aligned.m8n8.x4.shared.b16 {%0,%1,%2,%3}, [%4];"
        : "=r"(r[0]), "=r"(r[1]), "=r"(r[2]), "=r"(r[3]) : "r"(addr));
}
__device__ __forceinline__ void cpa16(uint32_t dst, const void* src) {
    asm volatile("cp.async.ca.shared.global [%0], [%1], 16;" :: "r"(dst), "l"(src));
}
__device__ __forceinline__ void cpa_commit() {
    asm volatile("cp.async.commit_group;" ::: "memory");
}
template <int Nw>
__device__ __forceinline__ void cpa_wait() {
    asm volatile("cp.async.wait_group %0;" :: "n"(Nw) : "memory");
}

// ---------------------------------------------------------------------------
// K0a: weight transpose to fp16.  W[K][N] -> hi[n][k]
// ---------------------------------------------------------------------------
__global__ void wsplit_kernel(const float* __restrict__ W,
                              __half* __restrict__ hi, int K, int N) {
    long idx = (long)blockIdx.x * 256 + threadIdx.x;
    if (idx >= (long)K * N) return;
    int n = (int)(idx / K), k = (int)(idx % K);
    hi[idx] = __float2half_rn(W[(long)k * N + n]);
}

// K0b: activation convert
__global__ void xsplit_kernel(const float* __restrict__ X,
                              __half* __restrict__ hi, long n) {
    long i = (long)blockIdx.x * 256 + threadIdx.x;
    if (i < n) hi[i] = __float2half_rn(X[i]);
}

// ---------------------------------------------------------------------------
// K1: CPB MLP -> 16*sigmoid table; K1b: expand + fold mask
// ---------------------------------------------------------------------------
__global__ void cpb_kernel(const float* __restrict__ table,
                           const float* __restrict__ w1,
                           const float* __restrict__ b1,
                           const float* __restrict__ w2) {
    __shared__ float hid[512];
    int e = blockIdx.x;
    int tid = threadIdx.x;
    float t0 = table[e * 2 + 0], t1 = table[e * 2 + 1];
    hid[tid] = fmaxf(0.f, fmaf(t0, w1[tid], fmaf(t1, w1[512 + tid], b1[tid])));
    __syncthreads();
    if (tid < 12) {
        float s = 0.f;
        #pragma unroll 8
        for (int i = 0; i < 512; i++) s = fmaf(hid[i], w2[i * 12 + tid], s);
        g_btab[e * 12 + tid] = 16.f / (1.f + expf(-s));
    }
}

__global__ void bias_expand_kernel(const int* __restrict__ rpi,
                                   const float* __restrict__ mask) {
    int idx = blockIdx.x * 256 + threadIdx.x;
    if (idx >= 16 * 12 * 144 * 144) return;
    int rj = idx % (144 * 144);
    int wh = idx / (144 * 144);
    int h = wh % 12, wt = wh / 12;
    g_bias2[idx] = g_btab[rpi[rj] * 12 + h] + mask[wt * 144 * 144 + rj];
}

// ---------------------------------------------------------------------------
// fp16 GEMM: 128x128 tile, BK=32, 2-stage cp.async, 256 threads,
// 8 warps each 32x64 via mma.m16n8k16; fragment loads via ldmatrix.x4.
// MODE 0: qkv (A gathered; scatter epilogue, f32 out + q/v bias)
// MODE 1: bias, f32 out
// MODE 2: bias + exact GELU, fp16 out
// ---------------------------------------------------------------------------
template <int MODE, int Ncols, int Kdim>
__global__ void __launch_bounds__(256, 2) gemm_h1(
    const __half* __restrict__ A_g, const __half* __restrict__ B_g,
    const float* __restrict__ bias, const float* __restrict__ bias2,
    float* __restrict__ CoutF, __half* __restrict__ CoutH) {
    extern __shared__ uint32_t smw[];
    uint32_t sb = smem_u32(smw);

    int tid = threadIdx.x;
    int bx = blockIdx.x, by = blockIdx.y;
    int warp = tid >> 5, lane = tid & 31;
    int g = lane >> 2, t = lane & 3;
    int wm = (warp & 3) * 32, wn = (warp >> 2) * 64;
    constexpr int NCHUNK = Kdim / 32;

    // ldmatrix per-thread tile-row offsets (bytes within stage):
    // A x4 (m16k16): row = wm + mt*16 + (lane&15), 16B-sel = lane>>4
    uint32_t a_off = (uint32_t)((wm + (lane & 15)) * ST2 * 4 + (lane >> 4) * 16);
    // B x4 (two n8k16 tiles): row = wn + ntp*16 + (lane&7) + ((lane>>4)<<3),
    //                         16B-sel = (lane>>3)&1
    uint32_t b_off = (uint32_t)(BUFW * 4 +
        (wn + (lane & 7) + ((lane >> 4) << 3)) * ST2 * 4 + ((lane >> 3) & 1) * 16);

    // load map: each thread copies 2 chunks of A and 2 of B (16B each).
    int lrow = tid >> 1;
    int segb = (tid & 1) * 2;
    long arow;
    {
        int gr = by * 128 + lrow;
        arow = (MODE == 0) ? (long)win_src_row(gr) : (long)gr;
    }
    long brow = bx * 128 + lrow;

    auto load_stage = [&](int s, int kc) {
        uint32_t stb = sb + s * (STAGEW * 4);
        uint32_t da = stb + lrow * (ST2 * 4) + segb * 16;
        uint32_t db = da + BUFW * 4;
        const __half* ga = A_g + arow * Kdim + kc + segb * 8;
        const __half* gb = B_g + brow * Kdim + kc + segb * 8;
        cpa16(da,      ga);
        cpa16(da + 16, ga + 8);
        cpa16(db,      gb);
        cpa16(db + 16, gb + 8);
    };

    float acc[2][8][4];
    #pragma unroll
    for (int i = 0; i < 2; i++)
        #pragma unroll
        for (int j = 0; j < 8; j++)
            #pragma unroll
            for (int q = 0; q < 4; q++) acc[i][j][q] = 0.f;

    load_stage(0, 0);
    cpa_commit();

    for (int c = 0; c < NCHUNK; c++) {
        if (c + 1 < NCHUNK) load_stage((c + 1) & 1, (c + 1) * 32);
        cpa_commit();
        cpa_wait<1>();
        __syncthreads();
        uint32_t stb = sb + (c & 1) * (STAGEW * 4);
        #pragma unroll
        for (int kk = 0; kk < 2; kk++) {      // two k16 steps
            uint32_t kb = kk * 32;            // 8 halves = 16B *2? (8 words)
            uint32_t ah[2][4];
            ldsm_x4(ah[0], stb + a_off + kb);
            ldsm_x4(ah[1], stb + a_off + 16 * ST2 * 4 + kb);
            uint32_t bf[4][4];
            #pragma unroll
            for (int ntp = 0; ntp < 4; ntp++)
                ldsm_x4(bf[ntp], stb + b_off + ntp * 16 * ST2 * 4 + kb);
            #pragma unroll
            for (int ntp = 0; ntp < 4; ntp++) {
                #pragma unroll
                for (int mt = 0; mt < 2; mt++) {
                    mma16(acc[mt][2 * ntp + 0], ah[mt], &bf[ntp][0]);
                    mma16(acc[mt][2 * ntp + 1], ah[mt], &bf[ntp][2]);
                }
            }
        }
        __syncthreads();
    }

    // ---- epilogue ----
    int gr = by * 128 + wm + g;
    int gc = bx * 128 + wn + 2 * t;
    #pragma unroll
    for (int mt = 0; mt < 2; mt++) {
        int r0 = gr + mt * 16;
        #pragma unroll
        for (int nt = 0; nt < 8; nt++) {
            int c0 = gc + nt * 8;
            if (MODE == 0) {
                #pragma unroll
                for (int e = 0; e < 4; e++) {
                    int row = r0 + (e >> 1) * 8;
                    int col = c0 + (e & 1);
                    int wi = row / kN, tk = row - wi * kN;
                    int part = col / kC, cc = col - part * kC;
                    float bv = (part == 0) ? bias[cc] : (part == 2 ? bias2[cc] : 0.f);
                    g_scratch[(long)part * kSLOT +
                              (((long)(wi * kNH + (cc >> 5))) * kN + tk) * kHD + (cc & 31)]
                        = acc[mt][nt][e] + bv;
                }
            } else if (MODE == 1) {
                float b0 = bias[c0], b1 = bias[c0 + 1];
                float2 v;
                v.x = acc[mt][nt][0] + b0; v.y = acc[mt][nt][1] + b1;
                *(float2*)&CoutF[(long)r0 * Ncols + c0] = v;
                v.x = acc[mt][nt][2] + b0; v.y = acc[mt][nt][3] + b1;
                *(float2*)&CoutF[(long)(r0 + 8) * Ncols + c0] = v;
            } else {
                float b0 = bias[c0], b1 = bias[c0 + 1];
                #pragma unroll
                for (int hh = 0; hh < 2; hh++) {
                    float vx = acc[mt][nt][2 * hh + 0] + b0;
                    float vy = acc[mt][nt][2 * hh + 1] + b1;
                    vx = 0.5f * vx * (1.f + erff(vx * 0.70710678f));
                    vy = 0.5f * vy * (1.f + erff(vy * 0.70710678f));
                    long off = (long)(r0 + 8 * hh) * Ncols + c0;
                    *(__half2*)(CoutH + off) =
                        __halves2half2(__float2half_rn(vx), __float2half_rn(vy));
                }
            }
        }
    }
}

// ---------------------------------------------------------------------------
// K3: cosine attention, one block per (window, head). 160 threads, 1 row each.
// Fixed stabilizer mx = scale + 16.  Output: fp16 (proj operand).
// ---------------------------------------------------------------------------
__global__ void __launch_bounds__(160) attn_kernel(const float* __restrict__ lsc,
                                                   __half* __restrict__ Oh) {
    __shared__ float4 ks4[144 * 8];
    __shared__ float4 vs4[144 * 8];
    int bh = blockIdx.x;
    int wi = bh / kNH, h = bh - wi * kNH;
    int tid = threadIdx.x;

    const float4* qg = (const float4*)(g_scratch + 0 * kSLOT + (long)bh * kN * kHD);
    const float4* kg = (const float4*)(g_scratch + 1 * kSLOT + (long)bh * kN * kHD);
    const float4* vg = (const float4*)(g_scratch + 2 * kSLOT + (long)bh * kN * kHD);

    for (int i = tid; i < 144 * 8; i += 160) {
        ks4[i] = kg[i];
        vs4[i] = vg[i];
    }
    __syncthreads();
    if (tid < kN) {
        float s = 0.f;
        float4 kr[8];
        #pragma unroll
        for (int d = 0; d < 8; d++) {
            kr[d] = ks4[tid * 8 + d];
            s += kr[d].x * kr[d].x + kr[d].y * kr[d].y + kr[d].z * kr[d].z + kr[d].w * kr[d].w;
        }
        float inv = 1.f / fmaxf(sqrtf(s), 1e-12f);
        #pragma unroll
        for (int d = 0; d < 8; d++) {
            kr[d].x *= inv; kr[d].y *= inv; kr[d].z *= inv; kr[d].w *= inv;
            ks4[tid * 8 + d] = kr[d];
        }
    }
    __syncthreads();

    if (tid < kN) {
        int r = tid;
        float scale = __expf(fminf(lsc[h], 4.605170185988092f));
        float4 qr[8];
        float s = 0.f;
        #pragma unroll
        for (int d = 0; d < 8; d++) {
            qr[d] = qg[r * 8 + d];
            s += qr[d].x * qr[d].x + qr[d].y * qr[d].y + qr[d].z * qr[d].z + qr[d].w * qr[d].w;
        }
        float inv = scale / fmaxf(sqrtf(s), 1e-12f);
        #pragma unroll
        for (int d = 0; d < 8; d++) {
            qr[d].x *= inv; qr[d].y *= inv; qr[d].z *= inv; qr[d].w *= inv;
        }

        const float* comb = g_bias2 + ((long)((wi & 15) * kNH + h) * kN + r) * kN;
        float mx = scale + 16.f;
        float4 o[8];
        #pragma unroll
        for (int d = 0; d < 8; d++) o[d] = make_float4(0.f, 0.f, 0.f, 0.f);
        float sum = 0.f;
        for (int j = 0; j < kN; j++) {
            float tt = comb[j];
            #pragma unroll
            for (int d = 0; d < 8; d++) {
                float4 kv = ks4[j * 8 + d];
                tt = fmaf(qr[d].x, kv.x, tt);
                tt = fmaf(qr[d].y, kv.y, tt);
                tt = fmaf(qr[d].z, kv.z, tt);
                tt = fmaf(qr[d].w, kv.w, tt);
            }
            float e = __expf(tt - mx);
            sum += e;
            #pragma unroll
            for (int d = 0; d < 8; d++) {
                float4 vv = vs4[j * 8 + d];
                o[d].x = fmaf(e, vv.x, o[d].x);
                o[d].y = fmaf(e, vv.y, o[d].y);
                o[d].z = fmaf(e, vv.z, o[d].z);
                o[d].w = fmaf(e, vv.w, o[d].w);
            }
        }
        float rs = 1.f / sum;
        long obase = (long)(wi * kN + r) * kC + h * kHD;
        #pragma unroll
        for (int d = 0; d < 8; d++) {
            *(__half2*)(Oh + obase + 4 * d) =
                __halves2half2(__float2half_rn(o[d].x * rs), __float2half_rn(o[d].y * rs));
            *(__half2*)(Oh + obase + 4 * d + 2) =
                __halves2half2(__float2half_rn(o[d].z * rs), __float2half_rn(o[d].w * rs));
        }
    }
}

// ---------------------------------------------------------------------------
// LN + residual. SCATTER: window->image reorder + emit fp16 copy.
// ---------------------------------------------------------------------------
template <bool SCATTER>
__global__ void __launch_bounds__(128) ln_res_kernel(
    const float* __restrict__ src, const float* __restrict__ resid,
    const float* __restrict__ gam, const float* __restrict__ bet,
    float* __restrict__ out, __half* __restrict__ Sh) {
    int m = blockIdx.x;
    int dst = SCATTER ? win_src_row(m) : m;
    const float* row = src + (long)m * kC;
    int tid = threadIdx.x;
    float v0 = row[tid], v1 = row[tid + 128], v2 = row[tid + 256];
    float s = v0 + v1 + v2;
    float s2 = v0 * v0 + v1 * v1 + v2 * v2;
    #pragma unroll
    for (int o = 16; o > 0; o >>= 1) {
        s  += __shfl_xor_sync(0xffffffffu, s, o);
        s2 += __shfl_xor_sync(0xffffffffu, s2, o);
    }
    __shared__ float sh[8];
    int wid = tid >> 5, lane = tid & 31;
    if (lane == 0) { sh[wid] = s; sh[4 + wid] = s2; }
    __syncthreads();
    s  = sh[0] + sh[1] + sh[2] + sh[3];
    s2 = sh[4] + sh[5] + sh[6] + sh[7];
    float mean = s * (1.f / 384.f);
    float var = s2 * (1.f / 384.f) - mean * mean;
    float rstd = rsqrtf(var + 1e-5f);
    const float* rrow = resid + (long)dst * kC;
    float* orow = out + (long)dst * kC;
    #pragma unroll
    for (int q = 0; q < 3; q++) {
        int col = tid + 128 * q;
        float v = (q == 0 ? v0 : (q == 1 ? v1 : v2));
        float y = rrow[col] + (v - mean) * rstd * gam[col] + bet[col];
        orow[col] = y;
        if (SCATTER) Sh[(long)dst * kC + col] = __float2half_rn(y);
    }
}

// ---------------------------------------------------------------------------
extern "C" void kernel_launch(void* const* d_in, const int* in_sizes, int n_in,
                              void* d_out, int out_size) {
    const float* x    = (const float*)d_in[0];
    const float* tab  = (const float*)d_in[1];
    const int*   rpi  = (const int*)  d_in[2];
    const float* mask = (const float*)d_in[3];
    const float* qkvw = (const float*)d_in[4];
    const float* qb   = (const float*)d_in[5];
    const float* vb   = (const float*)d_in[6];
    const float* lsc  = (const float*)d_in[7];
    const float* w1   = (const float*)d_in[8];
    const float* b1   = (const float*)d_in[9];
    const float* w2   = (const float*)d_in[10];
    const float* pw   = (const float*)d_in[11];
    const float* pb   = (const float*)d_in[12];
    const float* n1g  = (const float*)d_in[13];
    const float* n1b  = (const float*)d_in[14];
    const float* n2g  = (const float*)d_in[15];
    const float* n2b  = (const float*)d_in[16];
    const float* f1w  = (const float*)d_in[17];
    const float* f1b  = (const float*)d_in[18];
    const float* f2w  = (const float*)d_in[19];
    const float* f2b  = (const float*)d_in[20];
    float* out = (float*)d_out;

    float* f = nullptr;
    cudaGetSymbolAddress((void**)&f, g_scratch);
    __half* whi = nullptr; cudaGetSymbolAddress((void**)&whi, g_whi);

    // scratch map
    __half* attn_h = (__half*)(f + 3 * kSLOT);
    __half* x_h    = (__half*)(f + 4 * kSLOT);   // reused as x1_h
    float*  proj_f = f + 5 * kSLOT;
    float*  x1_f   = f + 1 * kSLOT;
    __half* h_h    = (__half*)(f + 2 * kSLOT);   // kM x 1536 halves, spans s2,s3
    float*  y_f    = f + 7 * kSLOT;

    cudaFuncSetAttribute(gemm_h1<0, 1152, 384>, cudaFuncAttributeMaxDynamicSharedMemorySize, SMEM_DYN);
    cudaFuncSetAttribute(gemm_h1<1, 384, 384>,  cudaFuncAttributeMaxDynamicSharedMemorySize, SMEM_DYN);
    cudaFuncSetAttribute(gemm_h1<2, 1536, 384>, cudaFuncAttributeMaxDynamicSharedMemorySize, SMEM_DYN);
    cudaFuncSetAttribute(gemm_h1<1, 384, 1536>, cudaFuncAttributeMaxDynamicSharedMemorySize, SMEM_DYN);

    // 0. weight transposes (fp16 [n][k]) + x convert
    wsplit_kernel<<<(442368 + 255) / 256, 256>>>(qkvw, whi + OQKV, 384, 1152);
    wsplit_kernel<<<(147456 + 255) / 256, 256>>>(pw,  whi + OPROJ, 384, 384);
    wsplit_kernel<<<(589824 + 255) / 256, 256>>>(f1w, whi + OFC1,  384, 1536);
    wsplit_kernel<<<(589824 + 255) / 256, 256>>>(f2w, whi + OFC2,  1536, 384);
    xsplit_kernel<<<(int)((kSLOT + 255) / 256), 256>>>(x, x_h, kSLOT);

    // 1. CPB bias table + expansion (bias + mask combined)
    cpb_kernel<<<529, 512>>>(tab, w1, b1, w2);
    bias_expand_kernel<<<(16 * 12 * 144 * 144 + 255) / 256, 256>>>(rpi, mask);

    // 2. QKV GEMM (gathered A) -> q/k/v f32 slots
    gemm_h1<0, 1152, 384><<<dim3(9, 576), 256, SMEM_DYN>>>(
        x_h, whi + OQKV, qb, vb, nullptr, nullptr);

    // 3. attention -> attn_h
    attn_kernel<<<512 * kNH, 160>>>(lsc, attn_h);

    // 4. proj GEMM -> proj_f
    gemm_h1<1, 384, 384><<<dim3(3, 576), 256, SMEM_DYN>>>(
        attn_h, whi + OPROJ, pb, nullptr, proj_f, nullptr);

    // 5. LN1 + residual + scatter -> x1_f + x1_h
    ln_res_kernel<true><<<kM, 128>>>(proj_f, x, n1g, n1b, x1_f, x_h);

    // 6. fc1 + GELU -> h_h
    gemm_h1<2, 1536, 384><<<dim3(12, 576), 256, SMEM_DYN>>>(
        x_h, whi + OFC1, f1b, nullptr, nullptr, h_h);

    // 7. fc2 -> y_f
    gemm_h1<1, 384, 1536><<<dim3(3, 576), 256, SMEM_DYN>>>(
        h_h, whi + OFC2, f2b, nullptr, y_f, nullptr);

    // 8. final LN + residual -> out
    ln_res_kernel<false><<<kM, 128>>>(y_f, x1_f, n2g, n2b, out, nullptr);
}